// round 13
// baseline (speedup 1.0000x reference)
#include <cuda_runtime.h>
#include <cuda_bf16.h>
#include <cstdint>

#define DM   1024
#define NH   16
#define DH   64
#define TSEQ 2048
#define BSZ  2
#define BT   (BSZ*TSEQ)

// ---------------------------------------------------------------------------
// Scratch (static device globals — no allocation). hi/lo bf16 stored as words.
// ---------------------------------------------------------------------------
__device__ __align__(16) uint32_t g_x_hi[BT*DM/2],  g_x_lo[BT*DM/2];
__device__ __align__(16) uint32_t g_w_hi[4*DM*DM/2], g_w_lo[4*DM*DM/2]; // [z][N][K]
__device__ __align__(16) uint32_t g_q_hi[BSZ*NH*TSEQ*DH/2], g_q_lo[BSZ*NH*TSEQ*DH/2];
__device__ __align__(16) uint32_t g_k_hi[BSZ*NH*TSEQ*DH/2], g_k_lo[BSZ*NH*TSEQ*DH/2];
__device__ __align__(16) uint32_t g_vt_hi[BSZ*NH*DH*(TSEQ/2)], g_vt_lo[BSZ*NH*DH*(TSEQ/2)];
__device__ __align__(16) uint32_t g_ao_hi[BT*DM/2], g_ao_lo[BT*DM/2];

// ---------------------------------------------------------------------------
// helpers
// ---------------------------------------------------------------------------
__device__ __forceinline__ uint32_t smem_u32(const void* p) {
    uint32_t a;
    asm("{ .reg .u64 t; cvta.to.shared.u64 t, %1; cvt.u32.u64 %0, t; }"
        : "=r"(a) : "l"(p));
    return a;
}

__device__ __forceinline__ uint32_t pack2(float e0, float e1) {
    uint32_t r;
    asm("cvt.rn.bf16x2.f32 %0, %1, %2;" : "=r"(r) : "f"(e1), "f"(e0));
    return r;
}

__device__ __forceinline__ void split2(float x0, float x1, uint32_t& hi, uint32_t& lo) {
    hi = pack2(x0, x1);
    float h0 = __uint_as_float(hi << 16);
    float h1 = __uint_as_float(hi & 0xffff0000u);
    lo = pack2(x0 - h0, x1 - h1);
}

__device__ __forceinline__ void mma16(float* d, const uint32_t* a, const uint32_t* b) {
    asm("mma.sync.aligned.m16n8k16.row.col.f32.bf16.bf16.f32 "
        "{%0,%1,%2,%3}, {%4,%5,%6,%7}, {%8,%9}, {%0,%1,%2,%3};"
        : "+f"(d[0]), "+f"(d[1]), "+f"(d[2]), "+f"(d[3])
        : "r"(a[0]), "r"(a[1]), "r"(a[2]), "r"(a[3]), "r"(b[0]), "r"(b[1]));
}

__device__ __forceinline__ void ldsm4(uint32_t* r, uint32_t a) {
    asm volatile("ldmatrix.sync.aligned.m8n8.x4.shared.b16 {%0,%1,%2,%3}, [%4];"
                 : "=r"(r[0]), "=r"(r[1]), "=r"(r[2]), "=r"(r[3]) : "r"(a));
}

__device__ __forceinline__ void cp16(uint32_t saddr, const void* g) {
    asm volatile("cp.async.cg.shared.global [%0], [%1], 16;"
                 :: "r"(saddr), "l"(g) : "memory");
}
#define CP_COMMIT() asm volatile("cp.async.commit_group;" ::: "memory")
#define CP_WAIT(N)  asm volatile("cp.async.wait_group %0;" :: "n"(N) : "memory")

// ---------------------------------------------------------------------------
// GEMM (R11 winner, unchanged): 3-buffer pipeline, one barrier per K-iter.
// ---------------------------------------------------------------------------
__device__ __forceinline__ void gemm_stage(uint32_t sbase, int buf,
                                           const uint32_t* Ahi, const uint32_t* Alo,
                                           const uint32_t* Bhi, const uint32_t* Blo,
                                           int k0) {
    const int tid = threadIdx.x;
    const uint32_t s = sbase + (uint32_t)buf * 36864u;
    #pragma unroll
    for (int it = 0; it < 8; it++) {
        int lin = it * 256 + tid;
        int isB = lin >> 10;
        int r   = (lin >> 3) & 127;
        int c   = lin & 7;
        int ishi = (c < 4);
        int cc  = c & 3;
        const uint32_t* src = isB ? (ishi ? Bhi : Blo) : (ishi ? Ahi : Alo);
        const uint32_t* g = src + (size_t)r * 512 + (k0 >> 1) + cc * 4;
        uint32_t dstw = (uint32_t)(isB * 4608 + r * 36 + (ishi ? 0 : 16) + cc * 4);
        cp16(s + dstw * 4u, g);
    }
    CP_COMMIT();
}

__device__ __forceinline__ void gemm_compute(uint32_t A0, uint32_t B0,
                                             float acc[4][4][4]) {
    #pragma unroll
    for (int kk = 0; kk < 2; kk++) {
        uint32_t b01h[4], b01l[4], b23h[4], b23l[4];
        ldsm4(b01h, B0 + kk * 32);
        ldsm4(b01l, B0 + kk * 32 + 64);
        ldsm4(b23h, B0 + 2304 + kk * 32);
        ldsm4(b23l, B0 + 2304 + kk * 32 + 64);
        #pragma unroll
        for (int mt = 0; mt < 4; mt++) {
            uint32_t ah[4], al[4];
            ldsm4(ah, A0 + mt * 2304 + kk * 32);
            ldsm4(al, A0 + mt * 2304 + kk * 32 + 64);
            mma16(acc[mt][0], ah, b01h);     mma16(acc[mt][1], ah, b01h + 2);
            mma16(acc[mt][2], ah, b23h);     mma16(acc[mt][3], ah, b23h + 2);
            mma16(acc[mt][0], ah, b01l);     mma16(acc[mt][1], ah, b01l + 2);
            mma16(acc[mt][2], ah, b23l);     mma16(acc[mt][3], ah, b23l + 2);
            mma16(acc[mt][0], al, b01h);     mma16(acc[mt][1], al, b01h + 2);
            mma16(acc[mt][2], al, b23h);     mma16(acc[mt][3], al, b23h + 2);
        }
    }
}

__device__ __forceinline__ void gemm_main(const uint32_t* Ahi, const uint32_t* Alo,
                                          const uint32_t* Bhi, const uint32_t* Blo,
                                          float acc[4][4][4]) {
    extern __shared__ uint32_t dsm[];
    const uint32_t sbase = smem_u32(dsm);

    gemm_stage(sbase, 0, Ahi, Alo, Bhi, Blo, 0);
    gemm_stage(sbase, 1, Ahi, Alo, Bhi, Blo, 32);

    const int tid = threadIdx.x;
    const int wid = tid >> 5, lane = tid & 31;
    const int wm = wid & 1, wn = wid >> 1;

    const uint32_t aoff =
        (uint32_t)(((wm * 64 + (lane & 15)) * 36 + ((lane & 16) ? 4 : 0)) * 4);
    const uint32_t boff =
        (uint32_t)(((wn * 32 + (lane & 7) + ((lane & 16) >> 1)) * 36
                    + ((lane & 8) ? 4 : 0)) * 4);

    int cur = 0, nxt2 = 2;
    #pragma unroll 1
    for (int kt = 0; kt < 32; kt++) {
        if (kt < 31) CP_WAIT(1);
        else         CP_WAIT(0);
        __syncthreads();
        uint32_t base = sbase + (uint32_t)cur * 36864u;
        gemm_compute(base + aoff, base + boff + 18432u, acc);
        if (kt + 2 < 32)
            gemm_stage(sbase, nxt2, Ahi, Alo, Bhi, Blo, (kt + 2) * 32);
        cur  = (cur  == 2) ? 0 : cur + 1;
        nxt2 = (nxt2 == 2) ? 0 : nxt2 + 1;
    }
}

// ---------------------------------------------------------------------------
// Kernel 0a: split x -> x_hi, x_lo
// ---------------------------------------------------------------------------
__global__ __launch_bounds__(256) void split_x_kernel(const float* __restrict__ x) {
    int i = (blockIdx.x * 256 + threadIdx.x) * 4;
    float4 v = *(const float4*)&x[i];
    uint32_t h0, l0, h1, l1;
    split2(v.x, v.y, h0, l0);
    split2(v.z, v.w, h1, l1);
    *(uint2*)&g_x_hi[i >> 1] = make_uint2(h0, h1);
    *(uint2*)&g_x_lo[i >> 1] = make_uint2(l0, l1);
}

// ---------------------------------------------------------------------------
// Kernel 0b: transpose+split weights  W[k][n] -> w_hi/lo[z][n][k]
// ---------------------------------------------------------------------------
__global__ __launch_bounds__(256) void transpose_split_kernel(
    const float* __restrict__ wq, const float* __restrict__ wk,
    const float* __restrict__ wv, const float* __restrict__ wo)
{
    __shared__ float tile[32][33];
    const float* src = (blockIdx.z == 0) ? wq : (blockIdx.z == 1) ? wk
                       : (blockIdx.z == 2) ? wv : wo;
    __nv_bfloat16* dh = (__nv_bfloat16*)(g_w_hi + (size_t)blockIdx.z * DM * DM / 2);
    __nv_bfloat16* dl = (__nv_bfloat16*)(g_w_lo + (size_t)blockIdx.z * DM * DM / 2);
    int x = blockIdx.x * 32 + threadIdx.x;
    int y0 = blockIdx.y * 32;
    #pragma unroll
    for (int i = threadIdx.y; i < 32; i += 8)
        tile[i][threadIdx.x] = src[(size_t)(y0 + i) * DM + x];
    __syncthreads();
    int xo = blockIdx.y * 32 + threadIdx.x;
    int yo0 = blockIdx.x * 32;
    #pragma unroll
    for (int i = threadIdx.y; i < 32; i += 8) {
        float v = tile[threadIdx.x][i];
        __nv_bfloat16 h = __float2bfloat16(v);
        dh[(size_t)(yo0 + i) * DM + xo] = h;
        dl[(size_t)(yo0 + i) * DM + xo] = __float2bfloat16(v - __bfloat162float(h));
    }
}

// ---------------------------------------------------------------------------
// Kernel 1: QKV projection. grid (8, 32, 3), 256 threads.
// ---------------------------------------------------------------------------
__global__ __launch_bounds__(256, 2) void qkv_mma_kernel(
    const float* __restrict__ bq, const float* __restrict__ bk,
    const float* __restrict__ bv)
{
    const int z = blockIdx.z;
    const float* bias = (z == 0) ? bq : (z == 1) ? bk : bv;
    const int m0 = blockIdx.y * 128, n0 = blockIdx.x * 128;

    float acc[4][4][4];
    #pragma unroll
    for (int mt = 0; mt < 4; mt++)
        #pragma unroll
        for (int nt = 0; nt < 4; nt++)
            #pragma unroll
            for (int i = 0; i < 4; i++) acc[mt][nt][i] = 0.0f;

    gemm_main(g_x_hi + (size_t)m0 * 512, g_x_lo + (size_t)m0 * 512,
              g_w_hi + (size_t)z * (DM * DM / 2) + (size_t)n0 * 512,
              g_w_lo + (size_t)z * (DM * DM / 2) + (size_t)n0 * 512, acc);

    const int tid = threadIdx.x;
    const int wid = tid >> 5, lane = tid & 31;
    const int gid = lane >> 2, tig = lane & 3;
    const int wm = wid & 1, wn = wid >> 1;

    #pragma unroll
    for (int nt = 0; nt < 4; nt++) {
        int col = n0 + wn * 32 + nt * 8 + 2 * tig;
        int h = col >> 6, d = col & 63;
        float b0 = bias[col], b1 = bias[col + 1];
        #pragma unroll
        for (int mt = 0; mt < 4; mt++) {
            int row = m0 + wm * 64 + mt * 16 + gid;
            int b = row >> 11, t = row & 2047;
            int bh = b * NH + h;
            if (z == 2) {
                __nv_bfloat16* vh = (__nv_bfloat16*)g_vt_hi
                                    + (size_t)bh * 64 * TSEQ;
                __nv_bfloat16* vl = (__nv_bfloat16*)g_vt_lo
                                    + (size_t)bh * 64 * TSEQ;
                #pragma unroll
                for (int e = 0; e < 4; e++) {
                    float val = acc[mt][nt][e] + ((e & 1) ? b1 : b0);
                    int dd = d + (e & 1);
                    int tt = t + ((e & 2) ? 8 : 0);
                    __nv_bfloat16 hi = __float2bfloat16(val);
                    vh[(size_t)dd * TSEQ + tt] = hi;
                    vl[(size_t)dd * TSEQ + tt] =
                        __float2bfloat16(val - __bfloat162float(hi));
                }
            } else {
                size_t base = ((size_t)bh * TSEQ + t) << 6;
                float sc = (z == 0) ? 0.125f : 1.0f;
                uint32_t *ph = (z == 0) ? g_q_hi : g_k_hi;
                uint32_t *pl = (z == 0) ? g_q_lo : g_k_lo;
                uint32_t hi, lo;
                split2((acc[mt][nt][0] + b0) * sc, (acc[mt][nt][1] + b1) * sc, hi, lo);
                ph[(base + d) >> 1] = hi; pl[(base + d) >> 1] = lo;
                split2((acc[mt][nt][2] + b0) * sc, (acc[mt][nt][3] + b1) * sc, hi, lo);
                ph[(base + 512 + d) >> 1] = hi; pl[(base + 512 + d) >> 1] = lo;
            }
        }
    }
}

// ---------------------------------------------------------------------------
// Kernel 3: O projection. grid (8, 32), 256 threads.
// ---------------------------------------------------------------------------
__global__ __launch_bounds__(256, 2) void oproj_mma_kernel(
    const float* __restrict__ bo, float* __restrict__ out)
{
    const int m0 = blockIdx.y * 128, n0 = blockIdx.x * 128;

    float acc[4][4][4];
    #pragma unroll
    for (int mt = 0; mt < 4; mt++)
        #pragma unroll
        for (int nt = 0; nt < 4; nt++)
            #pragma unroll
            for (int i = 0; i < 4; i++) acc[mt][nt][i] = 0.0f;

    gemm_main(g_ao_hi + (size_t)m0 * 512, g_ao_lo + (size_t)m0 * 512,
              g_w_hi + (size_t)3 * (DM * DM / 2) + (size_t)n0 * 512,
              g_w_lo + (size_t)3 * (DM * DM / 2) + (size_t)n0 * 512, acc);

    const int tid = threadIdx.x;
    const int wid = tid >> 5, lane = tid & 31;
    const int gid = lane >> 2, tig = lane & 3;
    const int wm = wid & 1, wn = wid >> 1;

    #pragma unroll
    for (int nt = 0; nt < 4; nt++) {
        int col = n0 + wn * 32 + nt * 8 + 2 * tig;
        float b0 = bo[col], b1 = bo[col + 1];
        #pragma unroll
        for (int mt = 0; mt < 4; mt++) {
            int row = m0 + wm * 64 + mt * 16 + gid;
            *(float2*)&out[(size_t)row * DM + col] =
                make_float2(acc[mt][nt][0] + b0, acc[mt][nt][1] + b1);
            *(float2*)&out[(size_t)(row + 8) * DM + col] =
                make_float2(acc[mt][nt][2] + b0, acc[mt][nt][3] + b1);
        }
    }
}

// ---------------------------------------------------------------------------
// Kernel 2: causal flash attention, SPLIT-KV groups. BLOCK_M=64.
// Warps 0-3 (group 0): even KV tiles from buf0. Warps 4-7 (group 1): odd
// tiles from buf1. Private online softmax per group; one merge per pass.
// SMEM words: Qlo[64][36]=2304 | ml[256] @2304 | buf0 @2560 | buf1 @11264.
// ---------------------------------------------------------------------------
#define A_ML   2304
#define A_BUF  2560
__device__ __forceinline__ void attn_stage(uint32_t sbase, int kt, int buf,
                                           const uint32_t* kh, const uint32_t* kl,
                                           const uint32_t* vh, const uint32_t* vl)
{
    const int tid = threadIdx.x;
    uint32_t kb = sbase + (uint32_t)(A_BUF + buf * 8704) * 4u;
    uint32_t vb = kb + 4352u * 4u;
    #pragma unroll
    for (int it = 0; it < 8; it++) {
        int lin = it * 256 + tid;
        int isV = lin >> 10;
        int r = (lin >> 4) & 63;
        int c = lin & 15;
        int ishi = (c < 8);
        int cc = c & 7;
        const uint32_t* src;
        uint32_t dst;
        if (!isV) {
            src = (ishi ? kh : kl) + (size_t)(kt * 64 + r) * 32 + cc * 4;
            dst = kb + (uint32_t)(r * 68 + (ishi ? 0 : 32) + cc * 4) * 4u;
        } else {
            src = (ishi ? vh : vl) + (size_t)r * (TSEQ / 2) + kt * 32 + cc * 4;
            dst = vb + (uint32_t)(r * 68 + (ishi ? 0 : 32) + cc * 4) * 4u;
        }
        cp16(dst, src);
    }
    CP_COMMIT();
}

__global__ __launch_bounds__(256, 2) void attn_mma_kernel()
{
    extern __shared__ uint32_t dsm[];
    const uint32_t sbase = smem_u32(dsm);
    float* ml = (float*)(dsm + A_ML);

    const int tid = threadIdx.x;
    const int wid = tid >> 5, lane = tid & 31;
    const int gid = lane >> 2, tig = lane & 3;
    const int g  = wid >> 2;        // KV-tile group
    const int wg = wid & 3;         // warp within group -> 16 q-rows
    const int bh = blockIdx.y;
    const int b = bh >> 4, h = bh & 15;

    const uint32_t* kh = g_k_hi + (size_t)bh * TSEQ * 32;
    const uint32_t* kl = g_k_lo + (size_t)bh * TSEQ * 32;
    const uint32_t* vh = g_vt_hi + (size_t)bh * 64 * (TSEQ / 2);
    const uint32_t* vl = g_vt_lo + (size_t)bh * 64 * (TSEQ / 2);

    const int r0l = wg * 16 + gid;

    const uint32_t qoff =
        (uint32_t)(((wg * 16 + (lane & 15)) * 36 + ((lane & 16) ? 4 : 0)) * 4);
    const uint32_t kvoff =
        (uint32_t)((((lane & 7) + ((lane & 16) >> 1)) * 68
                    + ((lane & 8) ? 4 : 0)) * 4);
    // this group's fixed buffer
    const uint32_t Kb = sbase + (uint32_t)(A_BUF + g * 8704) * 4u + kvoff;
    const uint32_t Vb = Kb + 4352u * 4u;

    #pragma unroll 1
    for (int pass = 0; pass < 2; pass++) {
        const int qt = (pass == 0) ? (31 - (int)blockIdx.x) : (int)blockIdx.x;
        const uint32_t* qh = g_q_hi + ((size_t)bh * TSEQ + (size_t)qt * 64) * 32;
        const uint32_t* ql = g_q_lo + ((size_t)bh * TSEQ + (size_t)qt * 64) * 32;
        const int nkv = qt + 1;

        __syncthreads();   // prior pass fully done with smem

        // stage Q-lo (64 rows x 32 words; folds into stage-0 commit)
        #pragma unroll
        for (int it = 0; it < 2; it++) {
            int lin = it * 256 + tid;
            int r = lin >> 3, cc = lin & 7;
            cp16(sbase + (uint32_t)(r * 36 + cc * 4) * 4u, ql + (size_t)r * 32 + cc * 4);
        }
        attn_stage(sbase, 0, 0, kh, kl, vh, vl);
        if (nkv > 1) attn_stage(sbase, 1, 1, kh, kl, vh, vl);

        uint32_t qfh[4][4];
        #pragma unroll
        for (int ks = 0; ks < 4; ks++) {
            int w = ks * 8 + tig;
            qfh[ks][0] = qh[(size_t)r0l * 32 + w];
            qfh[ks][1] = qh[(size_t)(r0l + 8) * 32 + w];
            qfh[ks][2] = qh[(size_t)r0l * 32 + w + 4];
            qfh[ks][3] = qh[(size_t)(r0l + 8) * 32 + w + 4];
        }

        float o[8][4];
        #pragma unroll
        for (int nt = 0; nt < 8; nt++)
            #pragma unroll
            for (int i = 0; i < 4; i++) o[nt][i] = 0.0f;
        float m0 = -1e30f, m1 = -1e30f, l0 = 0.0f, l1 = 0.0f;

        const int nsup = (nkv + 1) >> 1;
        #pragma unroll 1
        for (int i = 0; i < nsup; i++) {
            const int t = 2 * i + g;
            CP_WAIT(0);
            __syncthreads();

            if (t < nkv) {
                // ---- S = Q @ K^T (this group's buffer) ----
                float s[8][4];
                #pragma unroll
                for (int nt = 0; nt < 8; nt++)
                    #pragma unroll
                    for (int j = 0; j < 4; j++) s[nt][j] = 0.0f;
                #pragma unroll
                for (int ks = 0; ks < 4; ks++) {
                    uint32_t qflr[4];
                    ldsm4(qflr, sbase + qoff + ks * 32);
                    #pragma unroll
                    for (int ntp = 0; ntp < 4; ntp++) {
                        uint32_t kh4[4], kl4[4];
                        ldsm4(kh4, Kb + ntp * 4352 + ks * 32);
                        ldsm4(kl4, Kb + ntp * 4352 + ks * 32 + 128);
                        mma16(s[2*ntp],   qfh[ks], kh4);
                        mma16(s[2*ntp+1], qfh[ks], kh4 + 2);
                        mma16(s[2*ntp],   qfh[ks], kl4);
                        mma16(s[2*ntp+1], qfh[ks], kl4 + 2);
                        mma16(s[2*ntp],   qflr,    kh4);
                        mma16(s[2*ntp+1], qflr,    kh4 + 2);
                    }
                }

                if (t == qt) {
                    int row0 = qt * 64 + r0l;
                    #pragma unroll
                    for (int nt = 0; nt < 8; nt++) {
                        int c0 = t * 64 + nt * 8 + 2 * tig;
                        if (c0 > row0)         s[nt][0] = -1e30f;
                        if (c0 + 1 > row0)     s[nt][1] = -1e30f;
                        if (c0 > row0 + 8)     s[nt][2] = -1e30f;
                        if (c0 + 1 > row0 + 8) s[nt][3] = -1e30f;
                    }
                }

                {
                    float rm0 = -1e30f, rm1 = -1e30f;
                    #pragma unroll
                    for (int nt = 0; nt < 8; nt++) {
                        rm0 = fmaxf(rm0, fmaxf(s[nt][0], s[nt][1]));
                        rm1 = fmaxf(rm1, fmaxf(s[nt][2], s[nt][3]));
                    }
                    #pragma unroll
                    for (int off = 1; off <= 2; off <<= 1) {
                        rm0 = fmaxf(rm0, __shfl_xor_sync(0xffffffffu, rm0, off, 4));
                        rm1 = fmaxf(rm1, __shfl_xor_sync(0xffffffffu, rm1, off, 4));
                    }
                    float mn0 = fmaxf(m0, rm0), mn1 = fmaxf(m1, rm1);
                    float cr0 = __expf(m0 - mn0), cr1 = __expf(m1 - mn1);
                    m0 = mn0; m1 = mn1;
                    float rs0 = 0.0f, rs1 = 0.0f;
                    #pragma unroll
                    for (int nt = 0; nt < 8; nt++) {
                        s[nt][0] = __expf(s[nt][0] - mn0);
                        s[nt][1] = __expf(s[nt][1] - mn0);
                        s[nt][2] = __expf(s[nt][2] - mn1);
                        s[nt][3] = __expf(s[nt][3] - mn1);
                        rs0 += s[nt][0] + s[nt][1];
                        rs1 += s[nt][2] + s[nt][3];
                    }
                    #pragma unroll
                    for (int off = 1; off <= 2; off <<= 1) {
                        rs0 += __shfl_xor_sync(0xffffffffu, rs0, off, 4);
                        rs1 += __shfl_xor_sync(0xffffffffu, rs1, off, 4);
                    }
                    l0 = l0 * cr0 + rs0;
                    l1 = l1 * cr1 + rs1;
                    #pragma unroll
                    for (int nt = 0; nt < 8; nt++) {
                        o[nt][0] *= cr0; o[nt][1] *= cr0;
                        o[nt][2] *= cr1; o[nt][3] *= cr1;
                    }
                }

                #pragma unroll
                for (int ks = 0; ks < 4; ks++) {
                    uint32_t ph[4], pl[4];
                    split2(s[2*ks][0],   s[2*ks][1],   ph[0], pl[0]);
                    split2(s[2*ks][2],   s[2*ks][3],   ph[1], pl[1]);
                    split2(s[2*ks+1][0], s[2*ks+1][1], ph[2], pl[2]);
                    split2(s[2*ks+1][2], s[2*ks+1][3], ph[3], pl[3]);
                    #pragma unroll
                    for (int ntp = 0; ntp < 4; ntp++) {
                        uint32_t vh4[4], vl4[4];
                        ldsm4(vh4, Vb + ntp * 4352 + ks * 32);
                        ldsm4(vl4, Vb + ntp * 4352 + ks * 32 + 128);
                        mma16(o[2*ntp],   ph, vh4);
                        mma16(o[2*ntp+1], ph, vh4 + 2);
                        mma16(o[2*ntp],   ph, vl4);
                        mma16(o[2*ntp+1], ph, vl4 + 2);
                        mma16(o[2*ntp],   pl, vh4);
                        mma16(o[2*ntp+1], pl, vh4 + 2);
                    }
                }
            }

            __syncthreads();
            if (2 * i + 2 < nkv) attn_stage(sbase, 2 * i + 2, 0, kh, kl, vh, vl);
            if (2 * i + 3 < nkv) attn_stage(sbase, 2 * i + 3, 1, kh, kl, vh, vl);
        }

        // ---- merge the two groups' softmax states (one per pass) ----
        CP_WAIT(0);
        __syncthreads();
        {
            float* obuf = (float*)(dsm + A_BUF);
            uint32_t wpos = (uint32_t)(wg * 1056 + lane * 33);
            if (g == 1) {
                #pragma unroll
                for (int nt = 0; nt < 8; nt++)
                    #pragma unroll
                    for (int i = 0; i < 4; i++)
                        obuf[wpos + nt * 4 + i] = o[nt][i];
                if (tig == 0) {
                    ml[r0l * 2]           = m0;
                    ml[r0l * 2 + 1]       = l0;
                    ml[(r0l + 8) * 2]     = m1;
                    ml[(r0l + 8) * 2 + 1] = l1;
                }
            }
            __syncthreads();
            if (g == 0) {
                float mB0 = ml[r0l * 2],       lB0 = ml[r0l * 2 + 1];
                float mB1 = ml[(r0l + 8) * 2], lB1 = ml[(r0l + 8) * 2 + 1];
                float mM0 = fmaxf(m0, mB0),    mM1 = fmaxf(m1, mB1);
                float a0 = __expf(m0 - mM0),   f0 = __expf(mB0 - mM0);
                float a1 = __expf(m1 - mM1),   f1 = __expf(mB1 - mM1);
                float inv0 = 1.0f / (l0 * a0 + lB0 * f0);
                float inv1 = 1.0f / (l1 * a1 + lB1 * f1);

                size_t row0 = (size_t)(b * TSEQ + qt * 64 + r0l);
                #pragma unroll
                for (int nt = 0; nt < 8; nt++) {
                    int c = nt * 8 + 2 * tig;
                    float v0 = (o[nt][0] * a0 + obuf[wpos + nt*4 + 0] * f0) * inv0;
                    float v1 = (o[nt][1] * a0 + obuf[wpos + nt*4 + 1] * f0) * inv0;
                    float v2 = (o[nt][2] * a1 + obuf[wpos + nt*4 + 2] * f1) * inv1;
                    float v3 = (o[nt][3] * a1 + obuf[wpos + nt*4 + 3] * f1) * inv1;
                    uint32_t hi, lo;
                    split2(v0, v1, hi, lo);
                    g_ao_hi[(row0 * DM + h * 64 + c) >> 1] = hi;
                    g_ao_lo[(row0 * DM + h * 64 + c) >> 1] = lo;
                    split2(v2, v3, hi, lo);
                    g_ao_hi[((row0 + 8) * DM + h * 64 + c) >> 1] = hi;
                    g_ao_lo[((row0 + 8) * DM + h * 64 + c) >> 1] = lo;
                }
            }
        }
    }
}

// ---------------------------------------------------------------------------
extern "C" void kernel_launch(void* const* d_in, const int* in_sizes, int n_in,
                              void* d_out, int out_size)
{
    const float* x  = (const float*)d_in[0];
    const float* wq = (const float*)d_in[1];
    const float* bq = (const float*)d_in[2];
    const float* wk = (const float*)d_in[3];
    const float* bk = (const float*)d_in[4];
    const float* wv = (const float*)d_in[5];
    const float* bv = (const float*)d_in[6];
    const float* wo = (const float*)d_in[7];
    const float* bo = (const float*)d_in[8];
    float* out = (float*)d_out;

    static const int GEMM_SMEM = 110592;                       // 3 x 36864
    static const int ATTN_SMEM = (2560 + 2 * 8704) * 4;        // 79872

    cudaFuncSetAttribute(qkv_mma_kernel,
                         cudaFuncAttributeMaxDynamicSharedMemorySize, GEMM_SMEM);
    cudaFuncSetAttribute(oproj_mma_kernel,
                         cudaFuncAttributeMaxDynamicSharedMemorySize, GEMM_SMEM);
    cudaFuncSetAttribute(attn_mma_kernel,
                         cudaFuncAttributeMaxDynamicSharedMemorySize, ATTN_SMEM);

    split_x_kernel<<<BT * DM / 1024, 256>>>(x);
    transpose_split_kernel<<<dim3(32, 32, 4), dim3(32, 8)>>>(wq, wk, wv, wo);

    qkv_mma_kernel<<<dim3(8, 32, 3), 256, GEMM_SMEM>>>(bq, bk, bv);

    attn_mma_kernel<<<dim3(16, BSZ * NH), 256, ATTN_SMEM>>>();

    oproj_mma_kernel<<<dim3(8, 32), 256, GEMM_SMEM>>>(bo, out);
}

// round 14
// speedup vs baseline: 1.0386x; 1.0386x over previous
#include <cuda_runtime.h>
#include <cuda_bf16.h>
#include <cstdint>

#define DM   1024
#define NH   16
#define DH   64
#define TSEQ 2048
#define BSZ  2
#define BT   (BSZ*TSEQ)

// ---------------------------------------------------------------------------
// Scratch (static device globals — no allocation). hi/lo bf16 stored as words.
// ---------------------------------------------------------------------------
__device__ __align__(16) uint32_t g_x_hi[BT*DM/2],  g_x_lo[BT*DM/2];
__device__ __align__(16) uint32_t g_w_hi[4*DM*DM/2], g_w_lo[4*DM*DM/2]; // [z][N][K]
__device__ __align__(16) uint32_t g_q_hi[BSZ*NH*TSEQ*DH/2], g_q_lo[BSZ*NH*TSEQ*DH/2];
__device__ __align__(16) uint32_t g_k_hi[BSZ*NH*TSEQ*DH/2], g_k_lo[BSZ*NH*TSEQ*DH/2];
__device__ __align__(16) uint32_t g_vt_hi[BSZ*NH*DH*(TSEQ/2)], g_vt_lo[BSZ*NH*DH*(TSEQ/2)];
__device__ __align__(16) uint32_t g_ao_hi[BT*DM/2], g_ao_lo[BT*DM/2];

// ---------------------------------------------------------------------------
// helpers
// ---------------------------------------------------------------------------
__device__ __forceinline__ uint32_t smem_u32(const void* p) {
    uint32_t a;
    asm("{ .reg .u64 t; cvta.to.shared.u64 t, %1; cvt.u32.u64 %0, t; }"
        : "=r"(a) : "l"(p));
    return a;
}

__device__ __forceinline__ uint32_t pack2(float e0, float e1) {
    uint32_t r;
    asm("cvt.rn.bf16x2.f32 %0, %1, %2;" : "=r"(r) : "f"(e1), "f"(e0));
    return r;
}

__device__ __forceinline__ void split2(float x0, float x1, uint32_t& hi, uint32_t& lo) {
    hi = pack2(x0, x1);
    float h0 = __uint_as_float(hi << 16);
    float h1 = __uint_as_float(hi & 0xffff0000u);
    lo = pack2(x0 - h0, x1 - h1);
}

// bare exp2 (same HW unit __expf uses, minus the log2e FMUL)
__device__ __forceinline__ float exp2a(float x) {
    float r;
    asm("ex2.approx.f32 %0, %1;" : "=f"(r) : "f"(x));
    return r;
}

__device__ __forceinline__ void mma16(float* d, const uint32_t* a, const uint32_t* b) {
    asm("mma.sync.aligned.m16n8k16.row.col.f32.bf16.bf16.f32 "
        "{%0,%1,%2,%3}, {%4,%5,%6,%7}, {%8,%9}, {%0,%1,%2,%3};"
        : "+f"(d[0]), "+f"(d[1]), "+f"(d[2]), "+f"(d[3])
        : "r"(a[0]), "r"(a[1]), "r"(a[2]), "r"(a[3]), "r"(b[0]), "r"(b[1]));
}

__device__ __forceinline__ void ldsm4(uint32_t* r, uint32_t a) {
    asm volatile("ldmatrix.sync.aligned.m8n8.x4.shared.b16 {%0,%1,%2,%3}, [%4];"
                 : "=r"(r[0]), "=r"(r[1]), "=r"(r[2]), "=r"(r[3]) : "r"(a));
}

__device__ __forceinline__ void cp16(uint32_t saddr, const void* g) {
    asm volatile("cp.async.cg.shared.global [%0], [%1], 16;"
                 :: "r"(saddr), "l"(g) : "memory");
}
#define CP_COMMIT() asm volatile("cp.async.commit_group;" ::: "memory")
#define CP_WAIT(N)  asm volatile("cp.async.wait_group %0;" :: "n"(N) : "memory")

// ---------------------------------------------------------------------------
// GEMM (R11 winner): 3-buffer pipeline, one barrier per K-iter.
// ---------------------------------------------------------------------------
__device__ __forceinline__ void gemm_stage(uint32_t sbase, int buf,
                                           const uint32_t* Ahi, const uint32_t* Alo,
                                           const uint32_t* Bhi, const uint32_t* Blo,
                                           int k0) {
    const int tid = threadIdx.x;
    const uint32_t s = sbase + (uint32_t)buf * 36864u;
    #pragma unroll
    for (int it = 0; it < 8; it++) {
        int lin = it * 256 + tid;
        int isB = lin >> 10;
        int r   = (lin >> 3) & 127;
        int c   = lin & 7;
        int ishi = (c < 4);
        int cc  = c & 3;
        const uint32_t* src = isB ? (ishi ? Bhi : Blo) : (ishi ? Ahi : Alo);
        const uint32_t* g = src + (size_t)r * 512 + (k0 >> 1) + cc * 4;
        uint32_t dstw = (uint32_t)(isB * 4608 + r * 36 + (ishi ? 0 : 16) + cc * 4);
        cp16(s + dstw * 4u, g);
    }
    CP_COMMIT();
}

__device__ __forceinline__ void gemm_compute(uint32_t A0, uint32_t B0,
                                             float acc[4][4][4]) {
    #pragma unroll
    for (int kk = 0; kk < 2; kk++) {
        uint32_t b01h[4], b01l[4], b23h[4], b23l[4];
        ldsm4(b01h, B0 + kk * 32);
        ldsm4(b01l, B0 + kk * 32 + 64);
        ldsm4(b23h, B0 + 2304 + kk * 32);
        ldsm4(b23l, B0 + 2304 + kk * 32 + 64);
        #pragma unroll
        for (int mt = 0; mt < 4; mt++) {
            uint32_t ah[4], al[4];
            ldsm4(ah, A0 + mt * 2304 + kk * 32);
            ldsm4(al, A0 + mt * 2304 + kk * 32 + 64);
            mma16(acc[mt][0], ah, b01h);     mma16(acc[mt][1], ah, b01h + 2);
            mma16(acc[mt][2], ah, b23h);     mma16(acc[mt][3], ah, b23h + 2);
            mma16(acc[mt][0], ah, b01l);     mma16(acc[mt][1], ah, b01l + 2);
            mma16(acc[mt][2], ah, b23l);     mma16(acc[mt][3], ah, b23l + 2);
            mma16(acc[mt][0], al, b01h);     mma16(acc[mt][1], al, b01h + 2);
            mma16(acc[mt][2], al, b23h);     mma16(acc[mt][3], al, b23h + 2);
        }
    }
}

__device__ __forceinline__ void gemm_main(const uint32_t* Ahi, const uint32_t* Alo,
                                          const uint32_t* Bhi, const uint32_t* Blo,
                                          float acc[4][4][4]) {
    extern __shared__ uint32_t dsm[];
    const uint32_t sbase = smem_u32(dsm);

    gemm_stage(sbase, 0, Ahi, Alo, Bhi, Blo, 0);
    gemm_stage(sbase, 1, Ahi, Alo, Bhi, Blo, 32);

    const int tid = threadIdx.x;
    const int wid = tid >> 5, lane = tid & 31;
    const int wm = wid & 1, wn = wid >> 1;

    const uint32_t aoff =
        (uint32_t)(((wm * 64 + (lane & 15)) * 36 + ((lane & 16) ? 4 : 0)) * 4);
    const uint32_t boff =
        (uint32_t)(((wn * 32 + (lane & 7) + ((lane & 16) >> 1)) * 36
                    + ((lane & 8) ? 4 : 0)) * 4);

    int cur = 0, nxt2 = 2;
    #pragma unroll 1
    for (int kt = 0; kt < 32; kt++) {
        if (kt < 31) CP_WAIT(1);
        else         CP_WAIT(0);
        __syncthreads();
        uint32_t base = sbase + (uint32_t)cur * 36864u;
        gemm_compute(base + aoff, base + boff + 18432u, acc);
        if (kt + 2 < 32)
            gemm_stage(sbase, nxt2, Ahi, Alo, Bhi, Blo, (kt + 2) * 32);
        cur  = (cur  == 2) ? 0 : cur + 1;
        nxt2 = (nxt2 == 2) ? 0 : nxt2 + 1;
    }
}

// ---------------------------------------------------------------------------
// Kernel 0a: split x -> x_hi, x_lo
// ---------------------------------------------------------------------------
__global__ __launch_bounds__(256) void split_x_kernel(const float* __restrict__ x) {
    int i = (blockIdx.x * 256 + threadIdx.x) * 4;
    float4 v = *(const float4*)&x[i];
    uint32_t h0, l0, h1, l1;
    split2(v.x, v.y, h0, l0);
    split2(v.z, v.w, h1, l1);
    *(uint2*)&g_x_hi[i >> 1] = make_uint2(h0, h1);
    *(uint2*)&g_x_lo[i >> 1] = make_uint2(l0, l1);
}

// ---------------------------------------------------------------------------
// Kernel 0b: transpose+split weights  W[k][n] -> w_hi/lo[z][n][k]
// ---------------------------------------------------------------------------
__global__ __launch_bounds__(256) void transpose_split_kernel(
    const float* __restrict__ wq, const float* __restrict__ wk,
    const float* __restrict__ wv, const float* __restrict__ wo)
{
    __shared__ float tile[32][33];
    const float* src = (blockIdx.z == 0) ? wq : (blockIdx.z == 1) ? wk
                       : (blockIdx.z == 2) ? wv : wo;
    __nv_bfloat16* dh = (__nv_bfloat16*)(g_w_hi + (size_t)blockIdx.z * DM * DM / 2);
    __nv_bfloat16* dl = (__nv_bfloat16*)(g_w_lo + (size_t)blockIdx.z * DM * DM / 2);
    int x = blockIdx.x * 32 + threadIdx.x;
    int y0 = blockIdx.y * 32;
    #pragma unroll
    for (int i = threadIdx.y; i < 32; i += 8)
        tile[i][threadIdx.x] = src[(size_t)(y0 + i) * DM + x];
    __syncthreads();
    int xo = blockIdx.y * 32 + threadIdx.x;
    int yo0 = blockIdx.x * 32;
    #pragma unroll
    for (int i = threadIdx.y; i < 32; i += 8) {
        float v = tile[threadIdx.x][i];
        __nv_bfloat16 h = __float2bfloat16(v);
        dh[(size_t)(yo0 + i) * DM + xo] = h;
        dl[(size_t)(yo0 + i) * DM + xo] = __float2bfloat16(v - __bfloat162float(h));
    }
}

// ---------------------------------------------------------------------------
// Kernel 1: QKV projection. grid (8, 32, 3), 256 threads.
// q (z=0): pre-scaled by 0.125*log2(e) (log2-domain attention scores).
// ---------------------------------------------------------------------------
__global__ __launch_bounds__(256, 2) void qkv_mma_kernel(
    const float* __restrict__ bq, const float* __restrict__ bk,
    const float* __restrict__ bv)
{
    const int z = blockIdx.z;
    const float* bias = (z == 0) ? bq : (z == 1) ? bk : bv;
    const int m0 = blockIdx.y * 128, n0 = blockIdx.x * 128;

    float acc[4][4][4];
    #pragma unroll
    for (int mt = 0; mt < 4; mt++)
        #pragma unroll
        for (int nt = 0; nt < 4; nt++)
            #pragma unroll
            for (int i = 0; i < 4; i++) acc[mt][nt][i] = 0.0f;

    gemm_main(g_x_hi + (size_t)m0 * 512, g_x_lo + (size_t)m0 * 512,
              g_w_hi + (size_t)z * (DM * DM / 2) + (size_t)n0 * 512,
              g_w_lo + (size_t)z * (DM * DM / 2) + (size_t)n0 * 512, acc);

    const int tid = threadIdx.x;
    const int wid = tid >> 5, lane = tid & 31;
    const int gid = lane >> 2, tig = lane & 3;
    const int wm = wid & 1, wn = wid >> 1;

    #pragma unroll
    for (int nt = 0; nt < 4; nt++) {
        int col = n0 + wn * 32 + nt * 8 + 2 * tig;
        int h = col >> 6, d = col & 63;
        float b0 = bias[col], b1 = bias[col + 1];
        #pragma unroll
        for (int mt = 0; mt < 4; mt++) {
            int row = m0 + wm * 64 + mt * 16 + gid;
            int b = row >> 11, t = row & 2047;
            int bh = b * NH + h;
            if (z == 2) {
                __nv_bfloat16* vh = (__nv_bfloat16*)g_vt_hi
                                    + (size_t)bh * 64 * TSEQ;
                __nv_bfloat16* vl = (__nv_bfloat16*)g_vt_lo
                                    + (size_t)bh * 64 * TSEQ;
                #pragma unroll
                for (int e = 0; e < 4; e++) {
                    float val = acc[mt][nt][e] + ((e & 1) ? b1 : b0);
                    int dd = d + (e & 1);
                    int tt = t + ((e & 2) ? 8 : 0);
                    __nv_bfloat16 hi = __float2bfloat16(val);
                    vh[(size_t)dd * TSEQ + tt] = hi;
                    vl[(size_t)dd * TSEQ + tt] =
                        __float2bfloat16(val - __bfloat162float(hi));
                }
            } else {
                size_t base = ((size_t)bh * TSEQ + t) << 6;
                // q pre-scale folds in log2(e): scores come out in log2 units
                float sc = (z == 0) ? 0.18033688011112042f : 1.0f;
                uint32_t *ph = (z == 0) ? g_q_hi : g_k_hi;
                uint32_t *pl = (z == 0) ? g_q_lo : g_k_lo;
                uint32_t hi, lo;
                split2((acc[mt][nt][0] + b0) * sc, (acc[mt][nt][1] + b1) * sc, hi, lo);
                ph[(base + d) >> 1] = hi; pl[(base + d) >> 1] = lo;
                split2((acc[mt][nt][2] + b0) * sc, (acc[mt][nt][3] + b1) * sc, hi, lo);
                ph[(base + 512 + d) >> 1] = hi; pl[(base + 512 + d) >> 1] = lo;
            }
        }
    }
}

// ---------------------------------------------------------------------------
// Kernel 3: O projection. grid (8, 32), 256 threads.
// ---------------------------------------------------------------------------
__global__ __launch_bounds__(256, 2) void oproj_mma_kernel(
    const float* __restrict__ bo, float* __restrict__ out)
{
    const int m0 = blockIdx.y * 128, n0 = blockIdx.x * 128;

    float acc[4][4][4];
    #pragma unroll
    for (int mt = 0; mt < 4; mt++)
        #pragma unroll
        for (int nt = 0; nt < 4; nt++)
            #pragma unroll
            for (int i = 0; i < 4; i++) acc[mt][nt][i] = 0.0f;

    gemm_main(g_ao_hi + (size_t)m0 * 512, g_ao_lo + (size_t)m0 * 512,
              g_w_hi + (size_t)3 * (DM * DM / 2) + (size_t)n0 * 512,
              g_w_lo + (size_t)3 * (DM * DM / 2) + (size_t)n0 * 512, acc);

    const int tid = threadIdx.x;
    const int wid = tid >> 5, lane = tid & 31;
    const int gid = lane >> 2, tig = lane & 3;
    const int wm = wid & 1, wn = wid >> 1;

    #pragma unroll
    for (int nt = 0; nt < 4; nt++) {
        int col = n0 + wn * 32 + nt * 8 + 2 * tig;
        float b0 = bo[col], b1 = bo[col + 1];
        #pragma unroll
        for (int mt = 0; mt < 4; mt++) {
            int row = m0 + wm * 64 + mt * 16 + gid;
            *(float2*)&out[(size_t)row * DM + col] =
                make_float2(acc[mt][nt][0] + b0, acc[mt][nt][1] + b1);
            *(float2*)&out[(size_t)(row + 8) * DM + col] =
                make_float2(acc[mt][nt][2] + b0, acc[mt][nt][3] + b1);
        }
    }
}

// ---------------------------------------------------------------------------
// Kernel 2: causal flash attention (R11 structure; log2-domain softmax).
// SMEM words: Qlo[128][36]=4608 | buf0 (K 64x68 + V 64x68)=8704 | buf1 8704
// ---------------------------------------------------------------------------
#define ATT_BUF0 4608
__device__ __forceinline__ void attn_stage(uint32_t sbase, int kt, int buf,
                                           const uint32_t* kh, const uint32_t* kl,
                                           const uint32_t* vh, const uint32_t* vl)
{
    const int tid = threadIdx.x;
    uint32_t kb = sbase + (uint32_t)(ATT_BUF0 + buf * 8704) * 4u;
    uint32_t vb = kb + 4352u * 4u;
    #pragma unroll
    for (int it = 0; it < 8; it++) {
        int lin = it * 256 + tid;
        int isV = lin >> 10;
        int r = (lin >> 4) & 63;
        int c = lin & 15;
        int ishi = (c < 8);
        int cc = c & 7;
        const uint32_t* src;
        uint32_t dst;
        if (!isV) {
            src = (ishi ? kh : kl) + (size_t)(kt * 64 + r) * 32 + cc * 4;
            dst = kb + (uint32_t)(r * 68 + (ishi ? 0 : 32) + cc * 4) * 4u;
        } else {
            src = (ishi ? vh : vl) + (size_t)r * (TSEQ / 2) + kt * 32 + cc * 4;
            dst = vb + (uint32_t)(r * 68 + (ishi ? 0 : 32) + cc * 4) * 4u;
        }
        cp16(dst, src);
    }
    CP_COMMIT();
}

__global__ __launch_bounds__(256, 2) void attn_mma_kernel()
{
    extern __shared__ uint32_t dsm[];
    const uint32_t sbase = smem_u32(dsm);

    const int tid = threadIdx.x;
    const int wid = tid >> 5, lane = tid & 31;
    const int gid = lane >> 2, tig = lane & 3;
    const int bh = blockIdx.y;
    const int b = bh >> 4, h = bh & 15;

    const uint32_t* kh = g_k_hi + (size_t)bh * TSEQ * 32;
    const uint32_t* kl = g_k_lo + (size_t)bh * TSEQ * 32;
    const uint32_t* vh = g_vt_hi + (size_t)bh * 64 * (TSEQ / 2);
    const uint32_t* vl = g_vt_lo + (size_t)bh * 64 * (TSEQ / 2);

    const int r0l = wid * 16 + gid;

    const uint32_t qoff =
        (uint32_t)(((wid * 16 + (lane & 15)) * 36 + ((lane & 16) ? 4 : 0)) * 4);
    const uint32_t kvoff =
        (uint32_t)((((lane & 7) + ((lane & 16) >> 1)) * 68
                    + ((lane & 8) ? 4 : 0)) * 4);

    #pragma unroll 1
    for (int pass = 0; pass < 2; pass++) {
        const int qt = (pass == 0) ? (15 - (int)blockIdx.x) : (int)blockIdx.x;
        const uint32_t* qh = g_q_hi + ((size_t)bh * TSEQ + (size_t)qt * 128) * 32;
        const uint32_t* ql = g_q_lo + ((size_t)bh * TSEQ + (size_t)qt * 128) * 32;
        const int nkv = 2 * qt + 2;

        __syncthreads();

        #pragma unroll
        for (int it = 0; it < 4; it++) {
            int lin = it * 256 + tid;
            int r = lin >> 3, cc = lin & 7;
            cp16(sbase + (uint32_t)(r * 36 + cc * 4) * 4u, ql + (size_t)r * 32 + cc * 4);
        }
        attn_stage(sbase, 0, 0, kh, kl, vh, vl);
        attn_stage(sbase, 1, 1, kh, kl, vh, vl);

        uint32_t qfh[4][4];
        #pragma unroll
        for (int ks = 0; ks < 4; ks++) {
            int w = ks * 8 + tig;
            qfh[ks][0] = qh[(size_t)r0l * 32 + w];
            qfh[ks][1] = qh[(size_t)(r0l + 8) * 32 + w];
            qfh[ks][2] = qh[(size_t)r0l * 32 + w + 4];
            qfh[ks][3] = qh[(size_t)(r0l + 8) * 32 + w + 4];
        }

        float o[8][4];
        #pragma unroll
        for (int nt = 0; nt < 8; nt++)
            #pragma unroll
            for (int i = 0; i < 4; i++) o[nt][i] = 0.0f;
        float m0 = -1e30f, m1 = -1e30f, l0 = 0.0f, l1 = 0.0f;

        #pragma unroll 1
        for (int kt = 0; kt < nkv; kt++) {
            if (kt + 1 < nkv) CP_WAIT(1);
            else              CP_WAIT(0);
            __syncthreads();

            const uint32_t Kb = sbase + (uint32_t)(ATT_BUF0 + (kt & 1) * 8704) * 4u
                                + kvoff;
            const uint32_t Vb = Kb + 4352u * 4u;

            // ---- S (log2 units) = Qs @ K^T ----
            float s[8][4];
            #pragma unroll
            for (int nt = 0; nt < 8; nt++)
                #pragma unroll
                for (int i = 0; i < 4; i++) s[nt][i] = 0.0f;
            #pragma unroll
            for (int ks = 0; ks < 4; ks++) {
                uint32_t qflr[4];
                ldsm4(qflr, sbase + qoff + ks * 32);
                #pragma unroll
                for (int ntp = 0; ntp < 4; ntp++) {
                    uint32_t kh4[4], kl4[4];
                    ldsm4(kh4, Kb + ntp * 4352 + ks * 32);
                    ldsm4(kl4, Kb + ntp * 4352 + ks * 32 + 128);
                    mma16(s[2*ntp],   qfh[ks], kh4);
                    mma16(s[2*ntp+1], qfh[ks], kh4 + 2);
                    mma16(s[2*ntp],   qfh[ks], kl4);
                    mma16(s[2*ntp+1], qfh[ks], kl4 + 2);
                    mma16(s[2*ntp],   qflr,    kh4);
                    mma16(s[2*ntp+1], qflr,    kh4 + 2);
                }
            }

            if (kt >= 2 * qt) {
                int row0 = qt * 128 + r0l;
                #pragma unroll
                for (int nt = 0; nt < 8; nt++) {
                    int c0 = kt * 64 + nt * 8 + 2 * tig;
                    if (c0 > row0)         s[nt][0] = -1e30f;
                    if (c0 + 1 > row0)     s[nt][1] = -1e30f;
                    if (c0 > row0 + 8)     s[nt][2] = -1e30f;
                    if (c0 + 1 > row0 + 8) s[nt][3] = -1e30f;
                }
            }

            // ---- online softmax in log2 domain (ex2, no log2e FMULs) ----
            {
                float rm0 = -1e30f, rm1 = -1e30f;
                #pragma unroll
                for (int nt = 0; nt < 8; nt++) {
                    rm0 = fmaxf(rm0, fmaxf(s[nt][0], s[nt][1]));
                    rm1 = fmaxf(rm1, fmaxf(s[nt][2], s[nt][3]));
                }
                #pragma unroll
                for (int off = 1; off <= 2; off <<= 1) {
                    rm0 = fmaxf(rm0, __shfl_xor_sync(0xffffffffu, rm0, off, 4));
                    rm1 = fmaxf(rm1, __shfl_xor_sync(0xffffffffu, rm1, off, 4));
                }
                float mn0 = fmaxf(m0, rm0), mn1 = fmaxf(m1, rm1);
                float cr0 = exp2a(m0 - mn0), cr1 = exp2a(m1 - mn1);
                m0 = mn0; m1 = mn1;
                float rs0 = 0.0f, rs1 = 0.0f;
                #pragma unroll
                for (int nt = 0; nt < 8; nt++) {
                    s[nt][0] = exp2a(s[nt][0] - mn0);
                    s[nt][1] = exp2a(s[nt][1] - mn0);
                    s[nt][2] = exp2a(s[nt][2] - mn1);
                    s[nt][3] = exp2a(s[nt][3] - mn1);
                    rs0 += s[nt][0] + s[nt][1];
                    rs1 += s[nt][2] + s[nt][3];
                }
                #pragma unroll
                for (int off = 1; off <= 2; off <<= 1) {
                    rs0 += __shfl_xor_sync(0xffffffffu, rs0, off, 4);
                    rs1 += __shfl_xor_sync(0xffffffffu, rs1, off, 4);
                }
                l0 = l0 * cr0 + rs0;
                l1 = l1 * cr1 + rs1;
                #pragma unroll
                for (int nt = 0; nt < 8; nt++) {
                    o[nt][0] *= cr0; o[nt][1] *= cr0;
                    o[nt][2] *= cr1; o[nt][3] *= cr1;
                }
            }

            // ---- O += P @ V ----
            #pragma unroll
            for (int ks = 0; ks < 4; ks++) {
                uint32_t ph[4], pl[4];
                split2(s[2*ks][0],   s[2*ks][1],   ph[0], pl[0]);
                split2(s[2*ks][2],   s[2*ks][3],   ph[1], pl[1]);
                split2(s[2*ks+1][0], s[2*ks+1][1], ph[2], pl[2]);
                split2(s[2*ks+1][2], s[2*ks+1][3], ph[3], pl[3]);
                #pragma unroll
                for (int ntp = 0; ntp < 4; ntp++) {
                    uint32_t vh4[4], vl4[4];
                    ldsm4(vh4, Vb + ntp * 4352 + ks * 32);
                    ldsm4(vl4, Vb + ntp * 4352 + ks * 32 + 128);
                    mma16(o[2*ntp],   ph, vh4);
                    mma16(o[2*ntp+1], ph, vh4 + 2);
                    mma16(o[2*ntp],   ph, vl4);
                    mma16(o[2*ntp+1], ph, vl4 + 2);
                    mma16(o[2*ntp],   pl, vh4);
                    mma16(o[2*ntp+1], pl, vh4 + 2);
                }
            }

            __syncthreads();
            if (kt + 2 < nkv) attn_stage(sbase, kt + 2, kt & 1, kh, kl, vh, vl);
        }

        const float inv0 = 1.0f / l0, inv1 = 1.0f / l1;
        size_t row0 = (size_t)(b * TSEQ + qt * 128 + r0l);
        #pragma unroll
        for (int nt = 0; nt < 8; nt++) {
            int c = nt * 8 + 2 * tig;
            uint32_t hi, lo;
            split2(o[nt][0] * inv0, o[nt][1] * inv0, hi, lo);
            g_ao_hi[(row0 * DM + h * 64 + c) >> 1] = hi;
            g_ao_lo[(row0 * DM + h * 64 + c) >> 1] = lo;
            split2(o[nt][2] * inv1, o[nt][3] * inv1, hi, lo);
            g_ao_hi[((row0 + 8) * DM + h * 64 + c) >> 1] = hi;
            g_ao_lo[((row0 + 8) * DM + h * 64 + c) >> 1] = lo;
        }
    }
}

// ---------------------------------------------------------------------------
extern "C" void kernel_launch(void* const* d_in, const int* in_sizes, int n_in,
                              void* d_out, int out_size)
{
    const float* x  = (const float*)d_in[0];
    const float* wq = (const float*)d_in[1];
    const float* bq = (const float*)d_in[2];
    const float* wk = (const float*)d_in[3];
    const float* bk = (const float*)d_in[4];
    const float* wv = (const float*)d_in[5];
    const float* bv = (const float*)d_in[6];
    const float* wo = (const float*)d_in[7];
    const float* bo = (const float*)d_in[8];
    float* out = (float*)d_out;

    static const int GEMM_SMEM = 110592;                       // 3 x 36864
    static const int ATTN_SMEM = (4608 + 2 * 8704) * 4;        // 88064

    cudaFuncSetAttribute(qkv_mma_kernel,
                         cudaFuncAttributeMaxDynamicSharedMemorySize, GEMM_SMEM);
    cudaFuncSetAttribute(oproj_mma_kernel,
                         cudaFuncAttributeMaxDynamicSharedMemorySize, GEMM_SMEM);
    cudaFuncSetAttribute(attn_mma_kernel,
                         cudaFuncAttributeMaxDynamicSharedMemorySize, ATTN_SMEM);

    split_x_kernel<<<BT * DM / 1024, 256>>>(x);
    transpose_split_kernel<<<dim3(32, 32, 4), dim3(32, 8)>>>(wq, wk, wv, wo);

    qkv_mma_kernel<<<dim3(8, 32, 3), 256, GEMM_SMEM>>>(bq, bk, bv);

    attn_mma_kernel<<<dim3(8, BSZ * NH), 256, ATTN_SMEM>>>();

    oproj_mma_kernel<<<dim3(8, 32), 256, GEMM_SMEM>>>(bo, out);
}

// round 15
// speedup vs baseline: 1.0410x; 1.0022x over previous
#include <cuda_runtime.h>
#include <cuda_bf16.h>
#include <cstdint>

#define DM   1024
#define NH   16
#define DH   64
#define TSEQ 2048
#define BSZ  2
#define BT   (BSZ*TSEQ)

// ---------------------------------------------------------------------------
// Scratch (static device globals — no allocation). hi/lo bf16 stored as words.
// ---------------------------------------------------------------------------
__device__ __align__(16) uint32_t g_x_hi[BT*DM/2],  g_x_lo[BT*DM/2];
__device__ __align__(16) uint32_t g_w_hi[4*DM*DM/2], g_w_lo[4*DM*DM/2]; // [z][N][K]
__device__ __align__(16) uint32_t g_q_hi[BSZ*NH*TSEQ*DH/2], g_q_lo[BSZ*NH*TSEQ*DH/2];
__device__ __align__(16) uint32_t g_k_hi[BSZ*NH*TSEQ*DH/2], g_k_lo[BSZ*NH*TSEQ*DH/2];
__device__ __align__(16) uint32_t g_vt_hi[BSZ*NH*DH*(TSEQ/2)], g_vt_lo[BSZ*NH*DH*(TSEQ/2)];
__device__ __align__(16) uint32_t g_ao_hi[BT*DM/2], g_ao_lo[BT*DM/2];

// ---------------------------------------------------------------------------
// helpers
// ---------------------------------------------------------------------------
__device__ __forceinline__ uint32_t smem_u32(const void* p) {
    uint32_t a;
    asm("{ .reg .u64 t; cvta.to.shared.u64 t, %1; cvt.u32.u64 %0, t; }"
        : "=r"(a) : "l"(p));
    return a;
}

__device__ __forceinline__ uint32_t pack2(float e0, float e1) {
    uint32_t r;
    asm("cvt.rn.bf16x2.f32 %0, %1, %2;" : "=r"(r) : "f"(e1), "f"(e0));
    return r;
}

__device__ __forceinline__ void split2(float x0, float x1, uint32_t& hi, uint32_t& lo) {
    hi = pack2(x0, x1);
    float h0 = __uint_as_float(hi << 16);
    float h1 = __uint_as_float(hi & 0xffff0000u);
    lo = pack2(x0 - h0, x1 - h1);
}

__device__ __forceinline__ float exp2a(float x) {
    float r;
    asm("ex2.approx.f32 %0, %1;" : "=f"(r) : "f"(x));
    return r;
}

__device__ __forceinline__ void mma16(float* d, const uint32_t* a, const uint32_t* b) {
    asm("mma.sync.aligned.m16n8k16.row.col.f32.bf16.bf16.f32 "
        "{%0,%1,%2,%3}, {%4,%5,%6,%7}, {%8,%9}, {%0,%1,%2,%3};"
        : "+f"(d[0]), "+f"(d[1]), "+f"(d[2]), "+f"(d[3])
        : "r"(a[0]), "r"(a[1]), "r"(a[2]), "r"(a[3]), "r"(b[0]), "r"(b[1]));
}

__device__ __forceinline__ void ldsm4(uint32_t* r, uint32_t a) {
    asm volatile("ldmatrix.sync.aligned.m8n8.x4.shared.b16 {%0,%1,%2,%3}, [%4];"
                 : "=r"(r[0]), "=r"(r[1]), "=r"(r[2]), "=r"(r[3]) : "r"(a));
}

__device__ __forceinline__ void cp16(uint32_t saddr, const void* g) {
    asm volatile("cp.async.cg.shared.global [%0], [%1], 16;"
                 :: "r"(saddr), "l"(g) : "memory");
}
#define CP_COMMIT() asm volatile("cp.async.commit_group;" ::: "memory")
#define CP_WAIT(N)  asm volatile("cp.async.wait_group %0;" :: "n"(N) : "memory")

// ---------------------------------------------------------------------------
// GEMM (R11 winner): 3-buffer pipeline, one barrier per K-iter.
// ---------------------------------------------------------------------------
__device__ __forceinline__ void gemm_stage(uint32_t sbase, int buf,
                                           const uint32_t* Ahi, const uint32_t* Alo,
                                           const uint32_t* Bhi, const uint32_t* Blo,
                                           int k0) {
    const int tid = threadIdx.x;
    const uint32_t s = sbase + (uint32_t)buf * 36864u;
    #pragma unroll
    for (int it = 0; it < 8; it++) {
        int lin = it * 256 + tid;
        int isB = lin >> 10;
        int r   = (lin >> 3) & 127;
        int c   = lin & 7;
        int ishi = (c < 4);
        int cc  = c & 3;
        const uint32_t* src = isB ? (ishi ? Bhi : Blo) : (ishi ? Ahi : Alo);
        const uint32_t* g = src + (size_t)r * 512 + (k0 >> 1) + cc * 4;
        uint32_t dstw = (uint32_t)(isB * 4608 + r * 36 + (ishi ? 0 : 16) + cc * 4);
        cp16(s + dstw * 4u, g);
    }
    CP_COMMIT();
}

__device__ __forceinline__ void gemm_compute(uint32_t A0, uint32_t B0,
                                             float acc[4][4][4]) {
    #pragma unroll
    for (int kk = 0; kk < 2; kk++) {
        uint32_t b01h[4], b01l[4], b23h[4], b23l[4];
        ldsm4(b01h, B0 + kk * 32);
        ldsm4(b01l, B0 + kk * 32 + 64);
        ldsm4(b23h, B0 + 2304 + kk * 32);
        ldsm4(b23l, B0 + 2304 + kk * 32 + 64);
        #pragma unroll
        for (int mt = 0; mt < 4; mt++) {
            uint32_t ah[4], al[4];
            ldsm4(ah, A0 + mt * 2304 + kk * 32);
            ldsm4(al, A0 + mt * 2304 + kk * 32 + 64);
            mma16(acc[mt][0], ah, b01h);     mma16(acc[mt][1], ah, b01h + 2);
            mma16(acc[mt][2], ah, b23h);     mma16(acc[mt][3], ah, b23h + 2);
            mma16(acc[mt][0], ah, b01l);     mma16(acc[mt][1], ah, b01l + 2);
            mma16(acc[mt][2], ah, b23l);     mma16(acc[mt][3], ah, b23l + 2);
            mma16(acc[mt][0], al, b01h);     mma16(acc[mt][1], al, b01h + 2);
            mma16(acc[mt][2], al, b23h);     mma16(acc[mt][3], al, b23h + 2);
        }
    }
}

__device__ __forceinline__ void gemm_main(const uint32_t* Ahi, const uint32_t* Alo,
                                          const uint32_t* Bhi, const uint32_t* Blo,
                                          float acc[4][4][4]) {
    extern __shared__ uint32_t dsm[];
    const uint32_t sbase = smem_u32(dsm);

    gemm_stage(sbase, 0, Ahi, Alo, Bhi, Blo, 0);
    gemm_stage(sbase, 1, Ahi, Alo, Bhi, Blo, 32);

    const int tid = threadIdx.x;
    const int wid = tid >> 5, lane = tid & 31;
    const int wm = wid & 1, wn = wid >> 1;

    const uint32_t aoff =
        (uint32_t)(((wm * 64 + (lane & 15)) * 36 + ((lane & 16) ? 4 : 0)) * 4);
    const uint32_t boff =
        (uint32_t)(((wn * 32 + (lane & 7) + ((lane & 16) >> 1)) * 36
                    + ((lane & 8) ? 4 : 0)) * 4);

    int cur = 0, nxt2 = 2;
    #pragma unroll 1
    for (int kt = 0; kt < 32; kt++) {
        if (kt < 31) CP_WAIT(1);
        else         CP_WAIT(0);
        __syncthreads();
        uint32_t base = sbase + (uint32_t)cur * 36864u;
        gemm_compute(base + aoff, base + boff + 18432u, acc);
        if (kt + 2 < 32)
            gemm_stage(sbase, nxt2, Ahi, Alo, Bhi, Blo, (kt + 2) * 32);
        cur  = (cur  == 2) ? 0 : cur + 1;
        nxt2 = (nxt2 == 2) ? 0 : nxt2 + 1;
    }
}

// ---------------------------------------------------------------------------
// Kernel 0a: split x -> x_hi, x_lo
// ---------------------------------------------------------------------------
__global__ __launch_bounds__(256) void split_x_kernel(const float* __restrict__ x) {
    int i = (blockIdx.x * 256 + threadIdx.x) * 4;
    float4 v = *(const float4*)&x[i];
    uint32_t h0, l0, h1, l1;
    split2(v.x, v.y, h0, l0);
    split2(v.z, v.w, h1, l1);
    *(uint2*)&g_x_hi[i >> 1] = make_uint2(h0, h1);
    *(uint2*)&g_x_lo[i >> 1] = make_uint2(l0, l1);
}

// ---------------------------------------------------------------------------
// Kernel 0b: transpose+split weights  W[k][n] -> w_hi/lo[z][n][k]
// ---------------------------------------------------------------------------
__global__ __launch_bounds__(256) void transpose_split_kernel(
    const float* __restrict__ wq, const float* __restrict__ wk,
    const float* __restrict__ wv, const float* __restrict__ wo)
{
    __shared__ float tile[32][33];
    const float* src = (blockIdx.z == 0) ? wq : (blockIdx.z == 1) ? wk
                       : (blockIdx.z == 2) ? wv : wo;
    __nv_bfloat16* dh = (__nv_bfloat16*)(g_w_hi + (size_t)blockIdx.z * DM * DM / 2);
    __nv_bfloat16* dl = (__nv_bfloat16*)(g_w_lo + (size_t)blockIdx.z * DM * DM / 2);
    int x = blockIdx.x * 32 + threadIdx.x;
    int y0 = blockIdx.y * 32;
    #pragma unroll
    for (int i = threadIdx.y; i < 32; i += 8)
        tile[i][threadIdx.x] = src[(size_t)(y0 + i) * DM + x];
    __syncthreads();
    int xo = blockIdx.y * 32 + threadIdx.x;
    int yo0 = blockIdx.x * 32;
    #pragma unroll
    for (int i = threadIdx.y; i < 32; i += 8) {
        float v = tile[threadIdx.x][i];
        __nv_bfloat16 h = __float2bfloat16(v);
        dh[(size_t)(yo0 + i) * DM + xo] = h;
        dl[(size_t)(yo0 + i) * DM + xo] = __float2bfloat16(v - __bfloat162float(h));
    }
}

// ---------------------------------------------------------------------------
// Kernel 1: QKV projection. grid (8, 32, 3), 256 threads.
// q (z=0): pre-scaled by 0.125*log2(e).
// ---------------------------------------------------------------------------
__global__ __launch_bounds__(256, 2) void qkv_mma_kernel(
    const float* __restrict__ bq, const float* __restrict__ bk,
    const float* __restrict__ bv)
{
    const int z = blockIdx.z;
    const float* bias = (z == 0) ? bq : (z == 1) ? bk : bv;
    const int m0 = blockIdx.y * 128, n0 = blockIdx.x * 128;

    float acc[4][4][4];
    #pragma unroll
    for (int mt = 0; mt < 4; mt++)
        #pragma unroll
        for (int nt = 0; nt < 4; nt++)
            #pragma unroll
            for (int i = 0; i < 4; i++) acc[mt][nt][i] = 0.0f;

    gemm_main(g_x_hi + (size_t)m0 * 512, g_x_lo + (size_t)m0 * 512,
              g_w_hi + (size_t)z * (DM * DM / 2) + (size_t)n0 * 512,
              g_w_lo + (size_t)z * (DM * DM / 2) + (size_t)n0 * 512, acc);

    const int tid = threadIdx.x;
    const int wid = tid >> 5, lane = tid & 31;
    const int gid = lane >> 2, tig = lane & 3;
    const int wm = wid & 1, wn = wid >> 1;

    #pragma unroll
    for (int nt = 0; nt < 4; nt++) {
        int col = n0 + wn * 32 + nt * 8 + 2 * tig;
        int h = col >> 6, d = col & 63;
        float b0 = bias[col], b1 = bias[col + 1];
        #pragma unroll
        for (int mt = 0; mt < 4; mt++) {
            int row = m0 + wm * 64 + mt * 16 + gid;
            int b = row >> 11, t = row & 2047;
            int bh = b * NH + h;
            if (z == 2) {
                __nv_bfloat16* vh = (__nv_bfloat16*)g_vt_hi
                                    + (size_t)bh * 64 * TSEQ;
                __nv_bfloat16* vl = (__nv_bfloat16*)g_vt_lo
                                    + (size_t)bh * 64 * TSEQ;
                #pragma unroll
                for (int e = 0; e < 4; e++) {
                    float val = acc[mt][nt][e] + ((e & 1) ? b1 : b0);
                    int dd = d + (e & 1);
                    int tt = t + ((e & 2) ? 8 : 0);
                    __nv_bfloat16 hi = __float2bfloat16(val);
                    vh[(size_t)dd * TSEQ + tt] = hi;
                    vl[(size_t)dd * TSEQ + tt] =
                        __float2bfloat16(val - __bfloat162float(hi));
                }
            } else {
                size_t base = ((size_t)bh * TSEQ + t) << 6;
                float sc = (z == 0) ? 0.18033688011112042f : 1.0f;
                uint32_t *ph = (z == 0) ? g_q_hi : g_k_hi;
                uint32_t *pl = (z == 0) ? g_q_lo : g_k_lo;
                uint32_t hi, lo;
                split2((acc[mt][nt][0] + b0) * sc, (acc[mt][nt][1] + b1) * sc, hi, lo);
                ph[(base + d) >> 1] = hi; pl[(base + d) >> 1] = lo;
                split2((acc[mt][nt][2] + b0) * sc, (acc[mt][nt][3] + b1) * sc, hi, lo);
                ph[(base + 512 + d) >> 1] = hi; pl[(base + 512 + d) >> 1] = lo;
            }
        }
    }
}

// ---------------------------------------------------------------------------
// Kernel 3: O projection. grid (8, 32), 256 threads.
// ---------------------------------------------------------------------------
__global__ __launch_bounds__(256, 2) void oproj_mma_kernel(
    const float* __restrict__ bo, float* __restrict__ out)
{
    const int m0 = blockIdx.y * 128, n0 = blockIdx.x * 128;

    float acc[4][4][4];
    #pragma unroll
    for (int mt = 0; mt < 4; mt++)
        #pragma unroll
        for (int nt = 0; nt < 4; nt++)
            #pragma unroll
            for (int i = 0; i < 4; i++) acc[mt][nt][i] = 0.0f;

    gemm_main(g_ao_hi + (size_t)m0 * 512, g_ao_lo + (size_t)m0 * 512,
              g_w_hi + (size_t)3 * (DM * DM / 2) + (size_t)n0 * 512,
              g_w_lo + (size_t)3 * (DM * DM / 2) + (size_t)n0 * 512, acc);

    const int tid = threadIdx.x;
    const int wid = tid >> 5, lane = tid & 31;
    const int gid = lane >> 2, tig = lane & 3;
    const int wm = wid & 1, wn = wid >> 1;

    #pragma unroll
    for (int nt = 0; nt < 4; nt++) {
        int col = n0 + wn * 32 + nt * 8 + 2 * tig;
        float b0 = bo[col], b1 = bo[col + 1];
        #pragma unroll
        for (int mt = 0; mt < 4; mt++) {
            int row = m0 + wm * 64 + mt * 16 + gid;
            *(float2*)&out[(size_t)row * DM + col] =
                make_float2(acc[mt][nt][0] + b0, acc[mt][nt][1] + b1);
            *(float2*)&out[(size_t)(row + 8) * DM + col] =
                make_float2(acc[mt][nt][2] + b0, acc[mt][nt][3] + b1);
        }
    }
}

// ---------------------------------------------------------------------------
// Kernel 2: causal flash attention. R14 structure + deferred l-reduction
// + per-chunk fused exp/split/PV (overlaps MUFU with HMMA).
// SMEM words: Qlo[128][36]=4608 | buf0 (K 64x68 + V 64x68)=8704 | buf1 8704
// ---------------------------------------------------------------------------
#define ATT_BUF0 4608
__device__ __forceinline__ void attn_stage(uint32_t sbase, int kt, int buf,
                                           const uint32_t* kh, const uint32_t* kl,
                                           const uint32_t* vh, const uint32_t* vl)
{
    const int tid = threadIdx.x;
    uint32_t kb = sbase + (uint32_t)(ATT_BUF0 + buf * 8704) * 4u;
    uint32_t vb = kb + 4352u * 4u;
    #pragma unroll
    for (int it = 0; it < 8; it++) {
        int lin = it * 256 + tid;
        int isV = lin >> 10;
        int r = (lin >> 4) & 63;
        int c = lin & 15;
        int ishi = (c < 8);
        int cc = c & 7;
        const uint32_t* src;
        uint32_t dst;
        if (!isV) {
            src = (ishi ? kh : kl) + (size_t)(kt * 64 + r) * 32 + cc * 4;
            dst = kb + (uint32_t)(r * 68 + (ishi ? 0 : 32) + cc * 4) * 4u;
        } else {
            src = (ishi ? vh : vl) + (size_t)r * (TSEQ / 2) + kt * 32 + cc * 4;
            dst = vb + (uint32_t)(r * 68 + (ishi ? 0 : 32) + cc * 4) * 4u;
        }
        cp16(dst, src);
    }
    CP_COMMIT();
}

__global__ __launch_bounds__(256, 2) void attn_mma_kernel()
{
    extern __shared__ uint32_t dsm[];
    const uint32_t sbase = smem_u32(dsm);

    const int tid = threadIdx.x;
    const int wid = tid >> 5, lane = tid & 31;
    const int gid = lane >> 2, tig = lane & 3;
    const int bh = blockIdx.y;
    const int b = bh >> 4, h = bh & 15;

    const uint32_t* kh = g_k_hi + (size_t)bh * TSEQ * 32;
    const uint32_t* kl = g_k_lo + (size_t)bh * TSEQ * 32;
    const uint32_t* vh = g_vt_hi + (size_t)bh * 64 * (TSEQ / 2);
    const uint32_t* vl = g_vt_lo + (size_t)bh * 64 * (TSEQ / 2);

    const int r0l = wid * 16 + gid;

    const uint32_t qoff =
        (uint32_t)(((wid * 16 + (lane & 15)) * 36 + ((lane & 16) ? 4 : 0)) * 4);
    const uint32_t kvoff =
        (uint32_t)((((lane & 7) + ((lane & 16) >> 1)) * 68
                    + ((lane & 8) ? 4 : 0)) * 4);

    #pragma unroll 1
    for (int pass = 0; pass < 2; pass++) {
        const int qt = (pass == 0) ? (15 - (int)blockIdx.x) : (int)blockIdx.x;
        const uint32_t* qh = g_q_hi + ((size_t)bh * TSEQ + (size_t)qt * 128) * 32;
        const uint32_t* ql = g_q_lo + ((size_t)bh * TSEQ + (size_t)qt * 128) * 32;
        const int nkv = 2 * qt + 2;

        __syncthreads();

        #pragma unroll
        for (int it = 0; it < 4; it++) {
            int lin = it * 256 + tid;
            int r = lin >> 3, cc = lin & 7;
            cp16(sbase + (uint32_t)(r * 36 + cc * 4) * 4u, ql + (size_t)r * 32 + cc * 4);
        }
        attn_stage(sbase, 0, 0, kh, kl, vh, vl);
        attn_stage(sbase, 1, 1, kh, kl, vh, vl);

        uint32_t qfh[4][4];
        #pragma unroll
        for (int ks = 0; ks < 4; ks++) {
            int w = ks * 8 + tig;
            qfh[ks][0] = qh[(size_t)r0l * 32 + w];
            qfh[ks][1] = qh[(size_t)(r0l + 8) * 32 + w];
            qfh[ks][2] = qh[(size_t)r0l * 32 + w + 4];
            qfh[ks][3] = qh[(size_t)(r0l + 8) * 32 + w + 4];
        }

        float o[8][4];
        #pragma unroll
        for (int nt = 0; nt < 8; nt++)
            #pragma unroll
            for (int i = 0; i < 4; i++) o[nt][i] = 0.0f;
        // NOTE: l0/l1 are PER-LANE PARTIAL sums (reduced once in epilogue)
        float m0 = -1e30f, m1 = -1e30f, l0 = 0.0f, l1 = 0.0f;

        #pragma unroll 1
        for (int kt = 0; kt < nkv; kt++) {
            if (kt + 1 < nkv) CP_WAIT(1);
            else              CP_WAIT(0);
            __syncthreads();

            const uint32_t Kb = sbase + (uint32_t)(ATT_BUF0 + (kt & 1) * 8704) * 4u
                                + kvoff;
            const uint32_t Vb = Kb + 4352u * 4u;

            // ---- S (log2 units) = Qs @ K^T ----
            float s[8][4];
            #pragma unroll
            for (int nt = 0; nt < 8; nt++)
                #pragma unroll
                for (int i = 0; i < 4; i++) s[nt][i] = 0.0f;
            #pragma unroll
            for (int ks = 0; ks < 4; ks++) {
                uint32_t qflr[4];
                ldsm4(qflr, sbase + qoff + ks * 32);
                #pragma unroll
                for (int ntp = 0; ntp < 4; ntp++) {
                    uint32_t kh4[4], kl4[4];
                    ldsm4(kh4, Kb + ntp * 4352 + ks * 32);
                    ldsm4(kl4, Kb + ntp * 4352 + ks * 32 + 128);
                    mma16(s[2*ntp],   qfh[ks], kh4);
                    mma16(s[2*ntp+1], qfh[ks], kh4 + 2);
                    mma16(s[2*ntp],   qfh[ks], kl4);
                    mma16(s[2*ntp+1], qfh[ks], kl4 + 2);
                    mma16(s[2*ntp],   qflr,    kh4);
                    mma16(s[2*ntp+1], qflr,    kh4 + 2);
                }
            }

            if (kt >= 2 * qt) {
                int row0 = qt * 128 + r0l;
                #pragma unroll
                for (int nt = 0; nt < 8; nt++) {
                    int c0 = kt * 64 + nt * 8 + 2 * tig;
                    if (c0 > row0)         s[nt][0] = -1e30f;
                    if (c0 + 1 > row0)     s[nt][1] = -1e30f;
                    if (c0 > row0 + 8)     s[nt][2] = -1e30f;
                    if (c0 + 1 > row0 + 8) s[nt][3] = -1e30f;
                }
            }

            // ---- row max (the only in-loop cross-lane reduction) ----
            float mn0, mn1;
            {
                float rm0 = -1e30f, rm1 = -1e30f;
                #pragma unroll
                for (int nt = 0; nt < 8; nt++) {
                    rm0 = fmaxf(rm0, fmaxf(s[nt][0], s[nt][1]));
                    rm1 = fmaxf(rm1, fmaxf(s[nt][2], s[nt][3]));
                }
                #pragma unroll
                for (int off = 1; off <= 2; off <<= 1) {
                    rm0 = fmaxf(rm0, __shfl_xor_sync(0xffffffffu, rm0, off, 4));
                    rm1 = fmaxf(rm1, __shfl_xor_sync(0xffffffffu, rm1, off, 4));
                }
                mn0 = fmaxf(m0, rm0); mn1 = fmaxf(m1, rm1);
                float cr0 = exp2a(m0 - mn0), cr1 = exp2a(m1 - mn1);
                m0 = mn0; m1 = mn1;
                l0 *= cr0; l1 *= cr1;     // per-lane partial scales uniformly
                #pragma unroll
                for (int nt = 0; nt < 8; nt++) {
                    o[nt][0] *= cr0; o[nt][1] *= cr0;
                    o[nt][2] *= cr1; o[nt][3] *= cr1;
                }
            }

            // ---- fused per-chunk exp -> split -> PV (MUFU overlaps HMMA) ----
            #pragma unroll
            for (int ks = 0; ks < 4; ks++) {
                float e0 = exp2a(s[2*ks][0]   - mn0);
                float e1 = exp2a(s[2*ks][1]   - mn0);
                float e2 = exp2a(s[2*ks][2]   - mn1);
                float e3 = exp2a(s[2*ks][3]   - mn1);
                float e4 = exp2a(s[2*ks+1][0] - mn0);
                float e5 = exp2a(s[2*ks+1][1] - mn0);
                float e6 = exp2a(s[2*ks+1][2] - mn1);
                float e7 = exp2a(s[2*ks+1][3] - mn1);
                l0 += (e0 + e1) + (e4 + e5);
                l1 += (e2 + e3) + (e6 + e7);
                uint32_t ph[4], pl[4];
                split2(e0, e1, ph[0], pl[0]);
                split2(e2, e3, ph[1], pl[1]);
                split2(e4, e5, ph[2], pl[2]);
                split2(e6, e7, ph[3], pl[3]);
                #pragma unroll
                for (int ntp = 0; ntp < 4; ntp++) {
                    uint32_t vh4[4], vl4[4];
                    ldsm4(vh4, Vb + ntp * 4352 + ks * 32);
                    ldsm4(vl4, Vb + ntp * 4352 + ks * 32 + 128);
                    mma16(o[2*ntp],   ph, vh4);
                    mma16(o[2*ntp+1], ph, vh4 + 2);
                    mma16(o[2*ntp],   ph, vl4);
                    mma16(o[2*ntp+1], ph, vl4 + 2);
                    mma16(o[2*ntp],   pl, vh4);
                    mma16(o[2*ntp+1], pl, vh4 + 2);
                }
            }

            __syncthreads();
            if (kt + 2 < nkv) attn_stage(sbase, kt + 2, kt & 1, kh, kl, vh, vl);
        }

        // ---- epilogue: single l reduction, normalize, split, write ----
        #pragma unroll
        for (int off = 1; off <= 2; off <<= 1) {
            l0 += __shfl_xor_sync(0xffffffffu, l0, off, 4);
            l1 += __shfl_xor_sync(0xffffffffu, l1, off, 4);
        }
        const float inv0 = 1.0f / l0, inv1 = 1.0f / l1;
        size_t row0 = (size_t)(b * TSEQ + qt * 128 + r0l);
        #pragma unroll
        for (int nt = 0; nt < 8; nt++) {
            int c = nt * 8 + 2 * tig;
            uint32_t hi, lo;
            split2(o[nt][0] * inv0, o[nt][1] * inv0, hi, lo);
            g_ao_hi[(row0 * DM + h * 64 + c) >> 1] = hi;
            g_ao_lo[(row0 * DM + h * 64 + c) >> 1] = lo;
            split2(o[nt][2] * inv1, o[nt][3] * inv1, hi, lo);
            g_ao_hi[((row0 + 8) * DM + h * 64 + c) >> 1] = hi;
            g_ao_lo[((row0 + 8) * DM + h * 64 + c) >> 1] = lo;
        }
    }
}

// ---------------------------------------------------------------------------
extern "C" void kernel_launch(void* const* d_in, const int* in_sizes, int n_in,
                              void* d_out, int out_size)
{
    const float* x  = (const float*)d_in[0];
    const float* wq = (const float*)d_in[1];
    const float* bq = (const float*)d_in[2];
    const float* wk = (const float*)d_in[3];
    const float* bk = (const float*)d_in[4];
    const float* wv = (const float*)d_in[5];
    const float* bv = (const float*)d_in[6];
    const float* wo = (const float*)d_in[7];
    const float* bo = (const float*)d_in[8];
    float* out = (float*)d_out;

    static const int GEMM_SMEM = 110592;                       // 3 x 36864
    static const int ATTN_SMEM = (4608 + 2 * 8704) * 4;        // 88064

    cudaFuncSetAttribute(qkv_mma_kernel,
                         cudaFuncAttributeMaxDynamicSharedMemorySize, GEMM_SMEM);
    cudaFuncSetAttribute(oproj_mma_kernel,
                         cudaFuncAttributeMaxDynamicSharedMemorySize, GEMM_SMEM);
    cudaFuncSetAttribute(attn_mma_kernel,
                         cudaFuncAttributeMaxDynamicSharedMemorySize, ATTN_SMEM);

    split_x_kernel<<<BT * DM / 1024, 256>>>(x);
    transpose_split_kernel<<<dim3(32, 32, 4), dim3(32, 8)>>>(wq, wk, wv, wo);

    qkv_mma_kernel<<<dim3(8, 32, 3), 256, GEMM_SMEM>>>(bq, bk, bv);

    attn_mma_kernel<<<dim3(8, BSZ * NH), 256, ATTN_SMEM>>>();

    oproj_mma_kernel<<<dim3(8, 32), 256, GEMM_SMEM>>>(bo, out);
}